// round 11
// baseline (speedup 1.0000x reference)
#include <cuda_runtime.h>
#include <math.h>

// VectorExpansion: out[l, p, n] = sin(pi*x*(n+1)) / r * fc * norm * x^l
//   x = r/R_CUT, fc = x<1 ? 0.5*(cos(pi*x)+1) : 0, norm = sqrt(2/R_CUT)
// Output: [4, P, 8] f32
//
// R7: latency-exposure attack. 2 pair-halves per thread with all index
// loads + 4 random position gathers front-batched (MLP 2 -> 4+), half the
// warps, amortized block setup. Branchy zero path restored (R6 predication
// measured slower).

#define R_CUT_INV (1.0f / 5.0f)
#define NORM 0.6324555320336759f   /* sqrt(2/5) */
#define PI_F 3.14159265358979323846f

#define MAX_N 65536   // atoms (problem: 32768)
#define MAX_S 128     // structures (problem: 32)

__device__ float4 g_pos4[MAX_N];   // 1 MB scratch: padded positions

__global__ __launch_bounds__(256)
void pad_positions_kernel(const float* __restrict__ pos, int N)
{
    int i = blockIdx.x * blockDim.x + threadIdx.x;
    if (i < N) {
        g_pos4[i] = make_float4(pos[3 * i + 0], pos[3 * i + 1], pos[3 * i + 2], 0.0f);
    }
}

struct PairGeom {
    float x;   // r / R_CUT
    float r;
};

__device__ __forceinline__ void emit(float* obase, size_t stride_l,
                                     float x, float r, int n0)
{
    if (x >= 1.0f) {
        float4 z = make_float4(0.f, 0.f, 0.f, 0.f);
        #pragma unroll
        for (int l = 0; l < 4; l++)
            __stcs(reinterpret_cast<float4*>(obase + (size_t)l * stride_l), z);
        return;
    }

    float t1 = PI_F * x;
    float c1 = __cosf(t1);
    float fc = 0.5f * (c1 + 1.0f);

    float b[4];
    if (x >= 0.01f) {
        // Direct __sinf per harmonic: abs err ~4e-7 * pref(<13) -> <1e-5.
        float pref = fc * NORM / r;
        #pragma unroll
        for (int k = 0; k < 4; k++)
            b[k] = __sinf((float)(n0 + k) * t1) * pref;
    } else {
        // Small-r stable branch: sin(n*t)/r = (n*pi/R_CUT)*sinc(n*t);
        // t/r == pi/R_CUT exactly -> no sin/r cancellation.
        float scale = fc * NORM * (PI_F * R_CUT_INV);
        #pragma unroll
        for (int k = 0; k < 4; k++) {
            float fn = (float)(n0 + k);
            float u  = fn * t1;
            b[k] = scale * fn * (1.0f - u * u * (1.0f / 6.0f));
        }
    }

    float xl = 1.0f;
    #pragma unroll
    for (int l = 0; l < 4; l++) {
        __stcs(reinterpret_cast<float4*>(obase + (size_t)l * stride_l),
               make_float4(b[0] * xl, b[1] * xl, b[2] * xl, b[3] * xl));
        xl *= x;
    }
}

__global__ __launch_bounds__(256)
void vexp_kernel(const float*  __restrict__ cells,
                 const int*    __restrict__ shifts,
                 const int2*   __restrict__ pairs,
                 const int*    __restrict__ spair,
                 const int*    __restrict__ soff,
                 float*        __restrict__ out,
                 int P, int S)
{
    __shared__ float s_cells[MAX_S * 9];
    __shared__ int   s_soff[MAX_S];

    for (int i = threadIdx.x; i < S * 9; i += blockDim.x)
        s_cells[i] = cells[i];
    for (int i = threadIdx.x; i < S; i += blockDim.x)
        s_soff[i] = soff[i];
    __syncthreads();

    // Two threads per pair; each thread handles the SAME half of TWO pairs:
    // p0 = t>>1 in [0, Ph), p1 = p0 + Ph. Store addresses stay
    // lane-contiguous (512B/warp) on both iterations.
    const int Ph   = (P + 1) >> 1;
    int t    = blockIdx.x * blockDim.x + threadIdx.x;
    int p0   = t >> 1;
    int half = t & 1;
    if (p0 >= Ph) return;
    int p1 = p0 + Ph;
    bool do1 = (p1 < P);

    // ---- front-batched index loads (both pairs) ----
    const int  sp0 = __ldcs(&spair[p0]);
    const int2 pr0 = __ldcs(&pairs[p0]);
    const int  sh0x = __ldcs(&shifts[3 * p0 + 0]);
    const int  sh0y = __ldcs(&shifts[3 * p0 + 1]);
    const int  sh0z = __ldcs(&shifts[3 * p0 + 2]);

    int  sp1 = 0; int2 pr1 = make_int2(0, 0);
    int  sh1x = 0, sh1y = 0, sh1z = 0;
    if (do1) {
        sp1 = __ldcs(&spair[p1]);
        pr1 = __ldcs(&pairs[p1]);
        sh1x = __ldcs(&shifts[3 * p1 + 0]);
        sh1y = __ldcs(&shifts[3 * p1 + 1]);
        sh1z = __ldcs(&shifts[3 * p1 + 2]);
    }

    // ---- front-batched random gathers (4 independent LDG.128) ----
    const int off0 = s_soff[sp0];
    const float4 Pi0 = __ldg(&g_pos4[off0 + pr0.x]);
    const float4 Pj0 = __ldg(&g_pos4[off0 + pr0.y]);
    float4 Pi1 = make_float4(0, 0, 0, 0), Pj1 = Pi1;
    int off1 = 0;
    if (do1) {
        off1 = s_soff[sp1];
        Pi1 = __ldg(&g_pos4[off1 + pr1.x]);
        Pj1 = __ldg(&g_pos4[off1 + pr1.y]);
    }

    const size_t stride_l = (size_t)P * 8;
    const int n0 = 1 + half * 4;

    // ---- pair 0 ----
    {
        const float* c = s_cells + sp0 * 9;
        float fx = (float)sh0x, fy = (float)sh0y, fz = (float)sh0z;
        float vx = Pj0.x - Pi0.x + fx * c[0] + fy * c[3] + fz * c[6];
        float vy = Pj0.y - Pi0.y + fx * c[1] + fy * c[4] + fz * c[7];
        float vz = Pj0.z - Pi0.z + fx * c[2] + fy * c[5] + fz * c[8];
        float r  = sqrtf(fmaf(vx, vx, fmaf(vy, vy, fmaf(vz, vz, 1e-12f))));
        float x  = r * R_CUT_INV;
        emit(out + (size_t)p0 * 8 + half * 4, stride_l, x, r, n0);
    }

    // ---- pair 1 ----
    if (do1) {
        const float* c = s_cells + sp1 * 9;
        float fx = (float)sh1x, fy = (float)sh1y, fz = (float)sh1z;
        float vx = Pj1.x - Pi1.x + fx * c[0] + fy * c[3] + fz * c[6];
        float vy = Pj1.y - Pi1.y + fx * c[1] + fy * c[4] + fz * c[7];
        float vz = Pj1.z - Pi1.z + fx * c[2] + fy * c[5] + fz * c[8];
        float r  = sqrtf(fmaf(vx, vx, fmaf(vy, vy, fmaf(vz, vz, 1e-12f))));
        float x  = r * R_CUT_INV;
        emit(out + (size_t)p1 * 8 + half * 4, stride_l, x, r, n0);
    }
}

extern "C" void kernel_launch(void* const* d_in, const int* in_sizes, int n_in,
                              void* d_out, int out_size)
{
    const float* positions = (const float*)d_in[0];
    const float* cells     = (const float*)d_in[1];
    const int*   shifts    = (const int*)  d_in[3];
    const int2*  pairs     = (const int2*) d_in[5];
    const int*   spair     = (const int*)  d_in[7];
    const int*   soff      = (const int*)  d_in[8];
    float* out = (float*)d_out;

    int N = in_sizes[0] / 3;     // positions [N,3]
    int S = in_sizes[1] / 9;     // cells [S,3,3]
    int P = in_sizes[7];         // structure_pairs [P]

    pad_positions_kernel<<<(N + 255) / 256, 256>>>(positions, N);

    int Ph = (P + 1) >> 1;
    long long total = 2LL * Ph;          // 2 threads per pair, 2 pairs per thread
    int threads = 256;
    int blocks = (int)((total + threads - 1) / threads);
    vexp_kernel<<<blocks, threads>>>(cells, shifts, pairs, spair, soff,
                                     out, P, S);
}

// round 14
// speedup vs baseline: 1.3147x; 1.3147x over previous
#include <cuda_runtime.h>
#include <math.h>

// VectorExpansion: out[l, p, n] = sin(pi*x*(n+1)) / r * fc * norm * x^l
//   x = r/R_CUT, fc = x<1 ? 0.5*(cos(pi*x)+1) : 0, norm = sqrt(2/R_CUT)
// Output: [4, P, 8] f32
//
// R8: exact R5 structure (best measured: 60.2us kernel) + ONE change:
// position gathers use __ldcg (L2-only). The 512KB table thrashes 228KB L1
// (~70% miss -> fill+evict wavefronts, pure L1 overhead); in L2 it always
// hits. R6/R7 deltas (predication, ILP, __ldcs) are reverted - all measured
// as regressions.

#define R_CUT_INV (1.0f / 5.0f)
#define NORM 0.6324555320336759f   /* sqrt(2/5) */
#define PI_F 3.14159265358979323846f

#define MAX_N 65536   // atoms (problem: 32768)
#define MAX_S 128     // structures (problem: 32)

__device__ float4 g_pos4[MAX_N];   // 1 MB scratch: padded positions

__global__ __launch_bounds__(256)
void pad_positions_kernel(const float* __restrict__ pos, int N)
{
    int i = blockIdx.x * blockDim.x + threadIdx.x;
    if (i < N) {
        g_pos4[i] = make_float4(pos[3 * i + 0], pos[3 * i + 1], pos[3 * i + 2], 0.0f);
    }
}

__global__ __launch_bounds__(256)
void vexp_kernel(const float*  __restrict__ cells,
                 const int*    __restrict__ shifts,
                 const int2*   __restrict__ pairs,
                 const int*    __restrict__ spair,
                 const int*    __restrict__ soff,
                 float*        __restrict__ out,
                 int P, int S)
{
    __shared__ float s_cells[MAX_S * 9];
    __shared__ int   s_soff[MAX_S];

    for (int i = threadIdx.x; i < S * 9; i += blockDim.x)
        s_cells[i] = cells[i];
    for (int i = threadIdx.x; i < S; i += blockDim.x)
        s_soff[i] = soff[i];
    __syncthreads();

    // Two threads per pair: lanes (2k, 2k+1) share pair k's geometry;
    // half=0 handles n=1..4, half=1 handles n=5..8.
    int t    = blockIdx.x * blockDim.x + threadIdx.x;
    int p    = t >> 1;
    int half = t & 1;
    if (p >= P) return;

    const int sp  = __ldg(&spair[p]);
    const int off = s_soff[sp];
    const int2 pr = __ldg(&pairs[p]);

    const float fsx = (float)shifts[3 * p + 0];
    const float fsy = (float)shifts[3 * p + 1];
    const float fsz = (float)shifts[3 * p + 2];

    const float* c = s_cells + sp * 9;

    // L2-only gathers: random 16B from a 512KB table. Bypassing L1 removes
    // fill/evict wavefronts from a thrashing working set; L2 always hits.
    const float4 Pi = __ldcg(&g_pos4[off + pr.x]);
    const float4 Pj = __ldcg(&g_pos4[off + pr.y]);

    float vx = Pj.x - Pi.x + fsx * c[0] + fsy * c[3] + fsz * c[6];
    float vy = Pj.y - Pi.y + fsx * c[1] + fsy * c[4] + fsz * c[7];
    float vz = Pj.z - Pi.z + fsx * c[2] + fsy * c[5] + fsz * c[8];

    float r2 = fmaf(vx, vx, fmaf(vy, vy, fmaf(vz, vz, 1e-12f)));
    float r  = sqrtf(r2);
    float x  = r * R_CUT_INV;

    const size_t stride_l = (size_t)P * 8;                 // floats between l-slabs
    float* obase = out + (size_t)p * 8 + half * 4;         // lane-contiguous across warp

    if (x >= 1.0f) {
        // fc == 0 -> all outputs exactly zero.
        float4 z = make_float4(0.f, 0.f, 0.f, 0.f);
        #pragma unroll
        for (int l = 0; l < 4; l++)
            *reinterpret_cast<float4*>(obase + (size_t)l * stride_l) = z;
        return;
    }

    float t1 = PI_F * x;
    float c1 = __cosf(t1);
    float fc = 0.5f * (c1 + 1.0f);

    // This thread's 4 harmonics: n = n0..n0+3
    const int n0 = 1 + half * 4;
    float b[4];
    if (x < 0.01f) {
        // Small-r stable branch: sin(n*t)/r = (n*pi/R_CUT) * sinc(n*t),
        // t/r == pi/R_CUT exactly -> no sin/r cancellation.
        float scale = fc * NORM * (PI_F * R_CUT_INV);
        #pragma unroll
        for (int k = 0; k < 4; k++) {
            float fn = (float)(n0 + k);
            float u  = fn * t1;
            b[k] = scale * fn * (1.0f - u * u * (1.0f / 6.0f));
        }
    } else {
        // Direct __sinf per harmonic: abs err ~4e-7 * pref(<13) -> <1e-5.
        float pref = fc * NORM / r;
        #pragma unroll
        for (int k = 0; k < 4; k++)
            b[k] = __sinf((float)(n0 + k) * t1) * pref;
    }

    float xl = 1.0f;
    #pragma unroll
    for (int l = 0; l < 4; l++) {
        *reinterpret_cast<float4*>(obase + (size_t)l * stride_l) =
            make_float4(b[0] * xl, b[1] * xl, b[2] * xl, b[3] * xl);
        xl *= x;
    }
}

extern "C" void kernel_launch(void* const* d_in, const int* in_sizes, int n_in,
                              void* d_out, int out_size)
{
    const float* positions = (const float*)d_in[0];
    const float* cells     = (const float*)d_in[1];
    const int*   shifts    = (const int*)  d_in[3];
    const int2*  pairs     = (const int2*) d_in[5];
    const int*   spair     = (const int*)  d_in[7];
    const int*   soff      = (const int*)  d_in[8];
    float* out = (float*)d_out;

    int N = in_sizes[0] / 3;     // positions [N,3]
    int S = in_sizes[1] / 9;     // cells [S,3,3]
    int P = in_sizes[7];         // structure_pairs [P]

    pad_positions_kernel<<<(N + 255) / 256, 256>>>(positions, N);

    int threads = 256;
    long long total = 2LL * P;   // 2 threads per pair
    int blocks = (int)((total + threads - 1) / threads);
    vexp_kernel<<<blocks, threads>>>(cells, shifts, pairs, spair, soff,
                                     out, P, S);
}